// round 1
// baseline (speedup 1.0000x reference)
#include <cuda_runtime.h>
#include <math.h>

#define NN 4096
#define DD 64
#define LL 16
#define NT 32            // NN / 128 tiles per dim
#define NTRI 528         // NT*(NT+1)/2 triangular tile pairs
#define SURV_CAP (1 << 20)
#define D2_THRESH 50.0f  // exp(-25) cutoff; dropped mass < 1e-7 relative

// ---------------- device scratch (static, no allocation) ----------------
__device__ float g_xp[2][LL][NN][DD];   // packed [mat][l][i][d], 33.5 MB
__device__ float g_norm[2][LL][NN];     // squared norms
__device__ float g_r[2][LL][NN];        // row sums of K (init 1.0 = diagonal)
__device__ float g_S[LL];               // off-diagonal Sum Kx*Ky accumulation
__device__ int   g_scount;

struct Surv { int ml; int i; int j; float d2; };
__device__ Surv g_surv[SURV_CAP];

// ---------------- init ----------------
__global__ void init_kernel() {
    int idx = blockIdx.x * blockDim.x + threadIdx.x;
    if (idx < 2 * LL * NN) ((float*)g_r)[idx] = 1.0f;
    if (idx < LL) g_S[idx] = 0.0f;
    if (idx == 0) g_scount = 0;
}

// ---------------- pack: (N, D, L) strided -> [mat][l][i][d] contiguous + norms ----
__global__ void pack_kernel(const float* __restrict__ X, const float* __restrict__ Y) {
    __shared__ float buf[DD * LL];      // 1024 floats: buf[d*16 + l]
    const int m = blockIdx.y;
    const int i = blockIdx.x;
    const int t = threadIdx.x;
    const float* src = (m == 0 ? X : Y) + (size_t)i * (DD * LL);

#pragma unroll
    for (int q = 0; q < 4; ++q) buf[t + q * 256] = src[t + q * 256];
    __syncthreads();

#pragma unroll
    for (int q = 0; q < 4; ++q) {
        int e = t + q * 256;
        int l = e >> 6;
        int d = e & 63;
        g_xp[m][l][i][d] = buf[d * LL + l];
    }
    if (t < LL) {
        float s = 0.0f;
#pragma unroll
        for (int d = 0; d < DD; ++d) { float v = buf[d * LL + t]; s = fmaf(v, v, s); }
        g_norm[m][t][i] = s;
    }
}

// ---------------- main: 128x128x64 Gram tile + threshold epilogue ----------------
__global__ void __launch_bounds__(256, 2) gram_kernel() {
    // decode triangular tile pair (it <= jt)
    int p = blockIdx.x, it = 0, rem = NT;
    while (p >= rem) { p -= rem; rem--; it++; }
    const int jt = it + p;
    const int l = blockIdx.y;
    const int m = blockIdx.z;
    const int i0 = it * 128, j0 = jt * 128;

    const float* __restrict__ base = &g_xp[m][l][0][0];
    const float* __restrict__ nrm  = &g_norm[m][l][0];
    float* __restrict__ rrow = &g_r[m][l][0];

    __shared__ float As[32][132];
    __shared__ float Bs[32][132];
    __shared__ float nI[128], nJ[128];

    const int t = threadIdx.x;
    if (t < 128) nI[t] = nrm[i0 + t];
    else         nJ[t - 128] = nrm[j0 + t - 128];

    float acc[8][8];
#pragma unroll
    for (int a = 0; a < 8; ++a)
#pragma unroll
        for (int b = 0; b < 8; ++b) acc[a][b] = 0.0f;

    const int tx = t & 15, ty = t >> 4;
    const int mb = ty * 8, nb = tx * 8;

    for (int kc = 0; kc < DD; kc += 32) {
        __syncthreads();
#pragma unroll
        for (int q = 0; q < 4; ++q) {
            int idx = t + q * 256;          // 1024 float4 slots: 128 rows x 8
            int r = idx >> 3, kq = idx & 7;
            float4 va = *(const float4*)(base + (size_t)(i0 + r) * DD + kc + kq * 4);
            As[kq * 4 + 0][r] = va.x; As[kq * 4 + 1][r] = va.y;
            As[kq * 4 + 2][r] = va.z; As[kq * 4 + 3][r] = va.w;
            float4 vb = *(const float4*)(base + (size_t)(j0 + r) * DD + kc + kq * 4);
            Bs[kq * 4 + 0][r] = vb.x; Bs[kq * 4 + 1][r] = vb.y;
            Bs[kq * 4 + 2][r] = vb.z; Bs[kq * 4 + 3][r] = vb.w;
        }
        __syncthreads();
#pragma unroll
        for (int k = 0; k < 32; ++k) {
            float4 a0 = *(const float4*)&As[k][mb];
            float4 a1 = *(const float4*)&As[k][mb + 4];
            float4 b0 = *(const float4*)&Bs[k][nb];
            float4 b1 = *(const float4*)&Bs[k][nb + 4];
            float av[8] = {a0.x, a0.y, a0.z, a0.w, a1.x, a1.y, a1.z, a1.w};
            float bv[8] = {b0.x, b0.y, b0.z, b0.w, b1.x, b1.y, b1.z, b1.w};
#pragma unroll
            for (int mi = 0; mi < 8; ++mi)
#pragma unroll
                for (int ni = 0; ni < 8; ++ni)
                    acc[mi][ni] = fmaf(av[mi], bv[ni], acc[mi][ni]);
        }
    }

    // epilogue: d2 = |xi|^2 + |xj|^2 - 2 xi.xj ; only strict upper triangle
#pragma unroll
    for (int mi = 0; mi < 8; ++mi) {
        const int gi = i0 + mb + mi;
        const float ni_ = nI[mb + mi];
#pragma unroll
        for (int ni = 0; ni < 8; ++ni) {
            const int gj = j0 + nb + ni;
            float d2 = ni_ + nJ[nb + ni] - 2.0f * acc[mi][ni];
            if (gj > gi && d2 < D2_THRESH) {
                d2 = fmaxf(d2, 0.0f);
                float val = __expf(-0.5f * d2);
                atomicAdd(&rrow[gi], val);
                atomicAdd(&rrow[gj], val);
                int s = atomicAdd(&g_scount, 1);
                if (s < SURV_CAP) {
                    g_surv[s].ml = (l << 1) | m;
                    g_surv[s].i = gi; g_surv[s].j = gj; g_surv[s].d2 = d2;
                }
            }
        }
    }
}

// ---------------- survivors: cross-matrix product terms for S ----------------
__device__ __forceinline__ float dot64(const float* __restrict__ a, const float* __restrict__ b) {
    float s = 0.0f;
#pragma unroll
    for (int q = 0; q < 16; ++q) {
        float4 x = ((const float4*)a)[q];
        float4 y = ((const float4*)b)[q];
        s = fmaf(x.x, y.x, s); s = fmaf(x.y, y.y, s);
        s = fmaf(x.z, y.z, s); s = fmaf(x.w, y.w, s);
    }
    return s;
}

__global__ void surv_kernel() {
    int cnt = g_scount; if (cnt > SURV_CAP) cnt = SURV_CAP;
    for (int s = blockIdx.x * blockDim.x + threadIdx.x; s < cnt;
         s += gridDim.x * blockDim.x) {
        Surv v = g_surv[s];
        const int m = v.ml & 1;
        const int l = v.ml >> 1;
        const int om = m ^ 1;
        const float* bo = &g_xp[om][l][0][0];
        float d2o = g_norm[om][l][v.i] + g_norm[om][l][v.j]
                  - 2.0f * dot64(bo + (size_t)v.i * DD, bo + (size_t)v.j * DD);
        d2o = fmaxf(d2o, 0.0f);
        // dedup: a pair close in BOTH x and y would appear as survivor twice;
        // the x-side survivor owns it.
        if (m == 1 && d2o < D2_THRESH) continue;
        float stot = v.d2 + d2o;
        atomicAdd(&g_S[l], 2.0f * __expf(-0.5f * stot));  // x2: (i,j) and (j,i)
    }
}

// ---------------- finish: combine into HSIC sum ----------------
__global__ void finish_kernel(float* __restrict__ out) {
    __shared__ double sh0[256], sh1[256], sh2[256];
    const int t = threadIdx.x;
    double total = 0.0;
    const double n = (double)NN;

    for (int l = 0; l < LL; ++l) {
        const float* rx = &g_r[0][l][0];
        const float* ry = &g_r[1][l][0];
        double p = 0.0, sx = 0.0, sy = 0.0;
        for (int i = t; i < NN; i += 256) {
            double ax = (double)rx[i], ay = (double)ry[i];
            p += ax * ay; sx += ax; sy += ay;
        }
        sh0[t] = p; sh1[t] = sx; sh2[t] = sy;
        __syncthreads();
        for (int s = 128; s > 0; s >>= 1) {
            if (t < s) { sh0[t] += sh0[t + s]; sh1[t] += sh1[t + s]; sh2[t] += sh2[t + s]; }
            __syncthreads();
        }
        if (t == 0) {
            double S = n + (double)g_S[l];               // diagonal contributes n
            double num = S - 2.0 * sh0[0] / n + sh1[0] * sh2[0] / (n * n);
            total += num / ((n - 1.0) * (n - 1.0));
        }
        __syncthreads();
    }
    if (t == 0) out[0] = (float)total;
}

// ---------------- launch ----------------
extern "C" void kernel_launch(void* const* d_in, const int* in_sizes, int n_in,
                              void* d_out, int out_size) {
    const float* X = (const float*)d_in[0];
    const float* Y = (const float*)d_in[1];
    float* out = (float*)d_out;

    init_kernel<<<(2 * LL * NN + 255) / 256, 256>>>();
    pack_kernel<<<dim3(NN, 2), 256>>>(X, Y);
    gram_kernel<<<dim3(NTRI, LL, 2), 256>>>();
    surv_kernel<<<64, 256>>>();
    finish_kernel<<<1, 256>>>(out);
}

// round 3
// speedup vs baseline: 3.0273x; 3.0273x over previous
#include <cuda_runtime.h>
#include <cuda_bf16.h>
#include <cstdint>
#include <math.h>

#define NN 4096
#define DD 64
#define LL 16
#define NT 32            // NN / 128 tiles per dim
#define NTRI 528         // NT*(NT+1)/2 triangular tile pairs
#define SURV_CAP (1 << 20)
#define D2_THRESH 50.0f  // exp(-25) cutoff; dropped mass < 1e-7 relative
#define SMS 72           // padded smem row stride (bf16 elems): 144B, conflict-free ldmatrix

// ---------------- device scratch (static, no allocation) ----------------
__device__ float g_xp[2][LL][NN][DD];            // packed fp32 [mat][l][i][d]
__device__ __nv_bfloat16 g_xb[2][LL][NN][DD];    // packed bf16 row-major
__device__ float g_norm[2][LL][NN];              // squared norms
__device__ float g_r[2][LL][NN];                 // row sums of K (init 1 = diag)
__device__ float g_S[LL];                        // off-diag Sum Kx*Ky
__device__ int   g_scount;

struct Surv { int ml; int i; int j; };
__device__ Surv g_surv[SURV_CAP];

// ---------------- warp MMA helpers (portable sm_80+ path) ----------------
__device__ __forceinline__ uint32_t smem_u32(const void* p) {
    uint32_t a;
    asm("{ .reg .u64 t; cvta.to.shared.u64 t, %1; cvt.u32.u64 %0, t; }"
        : "=r"(a) : "l"(p));
    return a;
}
__device__ __forceinline__ void ldsm_x4(uint32_t* r, uint32_t addr) {
    asm volatile("ldmatrix.sync.aligned.m8n8.x4.shared.b16 {%0,%1,%2,%3}, [%4];"
                 : "=r"(r[0]), "=r"(r[1]), "=r"(r[2]), "=r"(r[3]) : "r"(addr));
}
__device__ __forceinline__ void mma16816(float* d, const uint32_t* a, uint32_t b0, uint32_t b1) {
    asm volatile("mma.sync.aligned.m16n8k16.row.col.f32.bf16.bf16.f32 "
                 "{%0,%1,%2,%3}, {%4,%5,%6,%7}, {%8,%9}, {%0,%1,%2,%3};"
                 : "+f"(d[0]), "+f"(d[1]), "+f"(d[2]), "+f"(d[3])
                 : "r"(a[0]), "r"(a[1]), "r"(a[2]), "r"(a[3]), "r"(b0), "r"(b1));
}

// ---------------- init ----------------
__global__ void init_kernel() {
    int idx = blockIdx.x * blockDim.x + threadIdx.x;
    if (idx < 2 * LL * NN) ((float*)g_r)[idx] = 1.0f;
    if (idx < LL) g_S[idx] = 0.0f;
    if (idx == 0) g_scount = 0;
}

// ---------------- pack: (N, D, L) -> fp32 + bf16 row-major + norms ----------
__global__ void pack_kernel(const float* __restrict__ X, const float* __restrict__ Y) {
    __shared__ float buf[DD * LL];      // buf[d*16 + l]
    const int m = blockIdx.y;
    const int i = blockIdx.x;
    const int t = threadIdx.x;
    const float* src = (m == 0 ? X : Y) + (size_t)i * (DD * LL);

#pragma unroll
    for (int q = 0; q < 4; ++q) buf[t + q * 256] = src[t + q * 256];
    __syncthreads();

#pragma unroll
    for (int q = 0; q < 4; ++q) {
        int e = t + q * 256;
        int l = e >> 6;
        int d = e & 63;
        float v = buf[d * LL + l];
        g_xp[m][l][i][d] = v;
        g_xb[m][l][i][d] = __float2bfloat16_rn(v);
    }
    if (t < LL) {
        float s = 0.0f;
#pragma unroll
        for (int d = 0; d < DD; ++d) { float v = buf[d * LL + t]; s = fmaf(v, v, s); }
        g_norm[m][t][i] = s;
    }
}

// ---------------- main: 128x128x64 HMMA Gram + threshold epilogue ------------
__global__ void __launch_bounds__(256) gram_kernel() {
    // decode triangular tile pair (it <= jt)
    int p = blockIdx.x, it = 0, rem = NT;
    while (p >= rem) { p -= rem; rem--; it++; }
    const int jt = it + p;
    const int l = blockIdx.y;
    const int m = blockIdx.z;
    const int i0 = it * 128, j0 = jt * 128;

    __shared__ __align__(16) __nv_bfloat16 As[128 * SMS];
    __shared__ __align__(16) __nv_bfloat16 Bs[128 * SMS];
    __shared__ float nI[128], nJ[128];

    const int t = threadIdx.x;
    const int w = t >> 5;
    const int lane = t & 31;
    const int wm = w >> 2;            // 0..1  -> 64-row band
    const int wn = w & 3;             // 0..3  -> 32-col band

    // fill smem tiles (row-major 64 -> padded 72)
    {
        const uint4* gA = (const uint4*)&g_xb[m][l][i0][0];   // 1024 chunks
        const uint4* gB = (const uint4*)&g_xb[m][l][j0][0];
#pragma unroll
        for (int q = 0; q < 4; ++q) {
            int idx = t + q * 256;
            int row = idx >> 3, c16 = idx & 7;
            *(uint4*)&As[row * SMS + c16 * 8] = gA[idx];
            *(uint4*)&Bs[row * SMS + c16 * 8] = gB[idx];
        }
        if (t < 128) nI[t] = g_norm[m][l][i0 + t];
        else         nJ[t - 128] = g_norm[m][l][j0 + t - 128];
    }
    __syncthreads();

    float acc[4][4][4];               // [m-frag][n8-frag][reg]
#pragma unroll
    for (int a = 0; a < 4; ++a)
#pragma unroll
        for (int b = 0; b < 4; ++b)
#pragma unroll
            for (int r = 0; r < 4; ++r) acc[a][b][r] = 0.0f;

    const int lrow = lane & 15;       // ldmatrix row select
    const int lcol = (lane >> 4) * 8; // ldmatrix col select (elements)

    const uint32_t aBase = smem_u32(As);
    const uint32_t bBase = smem_u32(Bs);

#pragma unroll
    for (int ks = 0; ks < 4; ++ks) {
        const int kc = ks * 16;
        uint32_t af[4][4], bf[2][4];
#pragma unroll
        for (int mf = 0; mf < 4; ++mf)
            ldsm_x4(af[mf], aBase + ((wm * 64 + mf * 16 + lrow) * SMS + kc + lcol) * 2);
#pragma unroll
        for (int nb = 0; nb < 2; ++nb)
            ldsm_x4(bf[nb], bBase + ((wn * 32 + nb * 16 + lrow) * SMS + kc + lcol) * 2);
#pragma unroll
        for (int mf = 0; mf < 4; ++mf)
#pragma unroll
            for (int j = 0; j < 4; ++j) {
                const int nb = j >> 1, hi = j & 1;
                mma16816(acc[mf][j], af[mf], bf[nb][hi], bf[nb][2 + hi]);
            }
    }

    // epilogue: d2 threshold, append survivors
    const int qrow = lane >> 2;
    const int qcol = (lane & 3) * 2;
#pragma unroll
    for (int mf = 0; mf < 4; ++mf) {
#pragma unroll
        for (int j = 0; j < 4; ++j) {
#pragma unroll
            for (int r = 0; r < 4; ++r) {
                const int li = wm * 64 + mf * 16 + qrow + ((r >> 1) << 3);
                const int lj = wn * 32 + j * 8 + qcol + (r & 1);
                const int gi = i0 + li;
                const int gj = j0 + lj;
                float d2 = nI[li] + nJ[lj] - 2.0f * acc[mf][j][r];
                if (gj > gi && d2 < D2_THRESH) {
                    int s = atomicAdd(&g_scount, 1);
                    if (s < SURV_CAP) {
                        g_surv[s].ml = (l << 1) | m;
                        g_surv[s].i = gi; g_surv[s].j = gj;
                    }
                }
            }
        }
    }
}

// ---------------- survivors: exact fp32 recompute + row sums + S -------------
__device__ __forceinline__ float dot64(const float* __restrict__ a, const float* __restrict__ b) {
    float s = 0.0f;
#pragma unroll
    for (int q = 0; q < 16; ++q) {
        float4 x = ((const float4*)a)[q];
        float4 y = ((const float4*)b)[q];
        s = fmaf(x.x, y.x, s); s = fmaf(x.y, y.y, s);
        s = fmaf(x.z, y.z, s); s = fmaf(x.w, y.w, s);
    }
    return s;
}

__global__ void surv_kernel() {
    int cnt = g_scount; if (cnt > SURV_CAP) cnt = SURV_CAP;
    for (int s = blockIdx.x * blockDim.x + threadIdx.x; s < cnt;
         s += gridDim.x * blockDim.x) {
        Surv v = g_surv[s];
        const int m = v.ml & 1;
        const int l = v.ml >> 1;
        const int om = m ^ 1;

        // exact own-matrix d2 (bf16 only gated the threshold)
        const float* bs = &g_xp[m][l][0][0];
        float d2s = g_norm[m][l][v.i] + g_norm[m][l][v.j]
                  - 2.0f * dot64(bs + (size_t)v.i * DD, bs + (size_t)v.j * DD);
        d2s = fmaxf(d2s, 0.0f);
        float val = __expf(-0.5f * d2s);
        atomicAdd(&g_r[m][l][v.i], val);
        atomicAdd(&g_r[m][l][v.j], val);

        // cross-matrix term for S
        const float* bo = &g_xp[om][l][0][0];
        float d2o = g_norm[om][l][v.i] + g_norm[om][l][v.j]
                  - 2.0f * dot64(bo + (size_t)v.i * DD, bo + (size_t)v.j * DD);
        d2o = fmaxf(d2o, 0.0f);
        // dedup: pair close in BOTH matrices appears twice; x-side (m=0) owns it
        if (m == 1 && d2o < D2_THRESH) continue;
        atomicAdd(&g_S[l], 2.0f * __expf(-0.5f * (d2s + d2o)));  // (i,j) and (j,i)
    }
}

// ---------------- finish: combine into HSIC sum ----------------
__global__ void finish_kernel(float* __restrict__ out) {
    __shared__ double sh0[256], sh1[256], sh2[256];
    const int t = threadIdx.x;
    double total = 0.0;
    const double n = (double)NN;

    for (int l = 0; l < LL; ++l) {
        const float* rx = &g_r[0][l][0];
        const float* ry = &g_r[1][l][0];
        double p = 0.0, sx = 0.0, sy = 0.0;
        for (int i = t; i < NN; i += 256) {
            double ax = (double)rx[i], ay = (double)ry[i];
            p += ax * ay; sx += ax; sy += ay;
        }
        sh0[t] = p; sh1[t] = sx; sh2[t] = sy;
        __syncthreads();
        for (int s = 128; s > 0; s >>= 1) {
            if (t < s) { sh0[t] += sh0[t + s]; sh1[t] += sh1[t + s]; sh2[t] += sh2[t + s]; }
            __syncthreads();
        }
        if (t == 0) {
            double S = n + (double)g_S[l];               // diagonal contributes n
            double num = S - 2.0 * sh0[0] / n + sh1[0] * sh2[0] / (n * n);
            total += num / ((n - 1.0) * (n - 1.0));
        }
        __syncthreads();
    }
    if (t == 0) out[0] = (float)total;
}

// ---------------- launch ----------------
extern "C" void kernel_launch(void* const* d_in, const int* in_sizes, int n_in,
                              void* d_out, int out_size) {
    const float* X = (const float*)d_in[0];
    const float* Y = (const float*)d_in[1];
    float* out = (float*)d_out;

    init_kernel<<<(2 * LL * NN + 255) / 256, 256>>>();
    pack_kernel<<<dim3(NN, 2), 256>>>(X, Y);
    gram_kernel<<<dim3(NTRI, LL, 2), 256>>>();
    surv_kernel<<<64, 256>>>();
    finish_kernel<<<1, 256>>>(out);
}